// round 7
// baseline (speedup 1.0000x reference)
#include <cuda_runtime.h>
#include <cuda_fp16.h>

#define MAX_N  100000
#define HID    16
#define SPLIT  50000          // nodes of g_gd resident in smem for scatter2
#define PBLK   148            // persistent grid: 1 CTA/SM (forced by 200KB smem)
#define PTHR   1024

// Scratch (allocation-free rule: __device__ globals)
__device__ float   g_deg[MAX_N];
__device__ float   g_dinv[MAX_N];
__device__ __align__(16) __half  g_px[MAX_N];   // fp16: dinv[v]*x[v]  (200KB)
__device__ float   g_s[MAX_N];                  // layer-1 aggregate accumulator
__device__ __align__(16) __half2 g_gd[MAX_N];   // fp16x2: dinv[v]*g[v,0:2] (400KB)
__device__ float2  g_acc[MAX_N];                // layer-2 aggregate accumulator

// one-op 2-float global reduction (sm_90+)
__device__ __forceinline__ void red_add_v2(float2* addr, float a, float b) {
    asm volatile("red.global.relaxed.gpu.add.v2.f32 [%0], {%1, %2};"
                 :: "l"(addr), "f"(a), "f"(b) : "memory");
}

__device__ __forceinline__ int4 ldcs_int4(const int* p) {
    return __ldcs(reinterpret_cast<const int4*>(p));
}

// degree histogram over dst, 4 edges/thread (measured optimum)
__global__ void k_deg(const int* __restrict__ dst, int E) {
    int i = blockIdx.x * blockDim.x + threadIdx.x;
    int base = i * 4;
    if (base + 3 < E) {
        int4 d = ldcs_int4(dst + base);
        atomicAdd(&g_deg[d.x], 1.0f);
        atomicAdd(&g_deg[d.y], 1.0f);
        atomicAdd(&g_deg[d.z], 1.0f);
        atomicAdd(&g_deg[d.w], 1.0f);
    } else {
        for (int j = base; j < E; ++j)
            atomicAdd(&g_deg[dst[j]], 1.0f);
    }
}

__global__ void k_dinv_px(const float* __restrict__ x, int n) {
    int i = blockIdx.x * blockDim.x + threadIdx.x;
    if (i < n) {
        float dv = rsqrtf(g_deg[i] + 1.0f);   // +1 = self-loop
        g_dinv[i] = dv;
        g_px[i]   = __float2half_rn(dv * x[i]);
    }
}

// scatter 1, persistent: px table in smem -> LDS gathers, RED f32 to global
__global__ void __launch_bounds__(PTHR, 1)
k_scatter1_p(const int* __restrict__ src, const int* __restrict__ dst, int E, int N) {
    extern __shared__ __half s_px[];
    // cooperative table load: N*2 bytes (N=100000 -> 12500 uint4, exact)
    {
        const uint4* gp = reinterpret_cast<const uint4*>(g_px);
        int nv = (N * 2) / 16;
        for (int i = threadIdx.x; i < nv; i += PTHR)
            reinterpret_cast<uint4*>(s_px)[i] = gp[i];
        for (int i = (nv * 16) / 2 + threadIdx.x; i < N; i += PTHR)  // tail halves
            s_px[i] = g_px[i];
    }
    __syncthreads();

    int tid  = blockIdx.x * PTHR + threadIdx.x;
    int nthr = gridDim.x * PTHR;
    int ngrp = E >> 2;
    for (int g = tid; g < ngrp; g += nthr) {
        int base = g * 4;
        int4 s4 = ldcs_int4(src + base);
        int4 d4 = ldcs_int4(dst + base);
        float p0 = __half2float(s_px[s4.x]);
        float p1 = __half2float(s_px[s4.y]);
        float p2 = __half2float(s_px[s4.z]);
        float p3 = __half2float(s_px[s4.w]);
        atomicAdd(&g_s[d4.x], p0);
        atomicAdd(&g_s[d4.y], p1);
        atomicAdd(&g_s[d4.z], p2);
        atomicAdd(&g_s[d4.w], p3);
    }
    if (tid == 0)  // edge-count tail (E%4)
        for (int j = ngrp * 4; j < E; ++j)
            atomicAdd(&g_s[dst[j]], __half2float(s_px[src[j]]));
}

// per-node dense: finalize s, W1/b1 + relu, W2 -> g, pre-scale by dinv
__global__ void k_node(const float* __restrict__ W1, const float* __restrict__ b1,
                       const float* __restrict__ W2, int n) {
    int v = blockIdx.x * blockDim.x + threadIdx.x;
    if (v >= n) return;
    float dv = g_dinv[v];
    float sv = dv * (g_s[v] + __half2float(g_px[v]));  // + self-loop term
    float g0 = 0.0f, g1 = 0.0f;
#pragma unroll
    for (int j = 0; j < HID; ++j) {
        float h = fmaxf(fmaf(sv, __ldg(&W1[j]), __ldg(&b1[j])), 0.0f);
        g0 = fmaf(h, __ldg(&W2[2 * j + 0]), g0);
        g1 = fmaf(h, __ldg(&W2[2 * j + 1]), g1);
    }
    g_gd[v] = __floats2half2_rn(dv * g0, dv * g1);
}

// scatter 2, persistent hybrid: gd[0:SPLIT) in smem, rest via predicated LDG
__global__ void __launch_bounds__(PTHR, 1)
k_scatter2_p(const int* __restrict__ src, const int* __restrict__ dst, int E) {
    extern __shared__ __half2 s_gd[];
    {
        const uint4* gp = reinterpret_cast<const uint4*>(g_gd);
        int nv = (SPLIT * 4) / 16;           // 12500, exact
        for (int i = threadIdx.x; i < nv; i += PTHR)
            reinterpret_cast<uint4*>(s_gd)[i] = gp[i];
    }
    __syncthreads();

    int tid  = blockIdx.x * PTHR + threadIdx.x;
    int nthr = gridDim.x * PTHR;
    int ngrp = E >> 2;
    for (int g = tid; g < ngrp; g += nthr) {
        int base = g * 4;
        int4 s4 = ldcs_int4(src + base);
        int4 d4 = ldcs_int4(dst + base);
        __half2 h0 = (s4.x < SPLIT) ? s_gd[s4.x] : __ldg(&g_gd[s4.x]);
        __half2 h1 = (s4.y < SPLIT) ? s_gd[s4.y] : __ldg(&g_gd[s4.y]);
        __half2 h2 = (s4.z < SPLIT) ? s_gd[s4.z] : __ldg(&g_gd[s4.z]);
        __half2 h3 = (s4.w < SPLIT) ? s_gd[s4.w] : __ldg(&g_gd[s4.w]);
        float2 a0 = __half22float2(h0);
        float2 a1 = __half22float2(h1);
        float2 a2 = __half22float2(h2);
        float2 a3 = __half22float2(h3);
        red_add_v2(&g_acc[d4.x], a0.x, a0.y);
        red_add_v2(&g_acc[d4.y], a1.x, a1.y);
        red_add_v2(&g_acc[d4.z], a2.x, a2.y);
        red_add_v2(&g_acc[d4.w], a3.x, a3.y);
    }
    if (tid == 0)
        for (int j = ngrp * 4; j < E; ++j) {
            int s = src[j];
            float2 a = __half22float2((s < SPLIT) ? s_gd[s] : __ldg(&g_gd[s]));
            red_add_v2(&g_acc[dst[j]], a.x, a.y);
        }
}

__global__ void k_final(const float* __restrict__ b2, float* __restrict__ out, int n) {
    int v = blockIdx.x * blockDim.x + threadIdx.x;
    if (v >= n) return;
    float dv = g_dinv[v];
    float2 acc = g_acc[v];
    float2 gd  = __half22float2(g_gd[v]);
    out[2 * v + 0] = dv * (acc.x + gd.x) + __ldg(&b2[0]);
    out[2 * v + 1] = dv * (acc.y + gd.y) + __ldg(&b2[1]);
}

extern "C" void kernel_launch(void* const* d_in, const int* in_sizes, int n_in,
                              void* d_out, int out_size) {
    const float* x  = (const float*)d_in[0];
    const int*   ei = (const int*)d_in[1];       // [2, E]: row0=src, row1=dst
    const float* W1 = (const float*)d_in[2];
    const float* b1 = (const float*)d_in[3];
    const float* W2 = (const float*)d_in[4];
    const float* b2 = (const float*)d_in[5];
    float* out = (float*)d_out;

    int N = in_sizes[0];                 // C_IN = 1
    int E = in_sizes[1] / 2;
    const int* src = ei;
    const int* dst = ei + E;

    const int T = 256;
    int gridN  = (N + T - 1) / T;
    int E4     = (E + 3) / 4;
    int gridE4 = (E4 + T - 1) / T;

    const int smem1 = N * 2;             // 200000 B px table
    const int smem2 = SPLIT * 4;         // 200000 B gd half-table
    cudaFuncSetAttribute(k_scatter1_p, cudaFuncAttributeMaxDynamicSharedMemorySize, smem1);
    cudaFuncSetAttribute(k_scatter2_p, cudaFuncAttributeMaxDynamicSharedMemorySize, smem2);

    // zero all accumulators via DMA (graph-capturable)
    void *degPtr = nullptr, *sPtr = nullptr, *accPtr = nullptr;
    cudaGetSymbolAddress(&degPtr, g_deg);
    cudaGetSymbolAddress(&sPtr,   g_s);
    cudaGetSymbolAddress(&accPtr, g_acc);
    cudaMemsetAsync(degPtr, 0, N * sizeof(float));
    cudaMemsetAsync(sPtr,   0, N * sizeof(float));
    cudaMemsetAsync(accPtr, 0, N * sizeof(float2));

    k_deg<<<gridE4, T>>>(dst, E);
    k_dinv_px<<<gridN, T>>>(x, N);
    k_scatter1_p<<<PBLK, PTHR, smem1>>>(src, dst, E, N);
    k_node<<<gridN, T>>>(W1, b1, W2, N);
    k_scatter2_p<<<PBLK, PTHR, smem2>>>(src, dst, E);
    k_final<<<gridN, T>>>(b2, out, N);
}

// round 8
// speedup vs baseline: 1.1275x; 1.1275x over previous
#include <cuda_runtime.h>
#include <cuda_fp16.h>

#define MAX_N 100000
#define HID   16

// Scratch (allocation-free rule: __device__ globals)
__device__ float   g_deg[MAX_N];
__device__ float   g_dinv[MAX_N];
__device__ __half  g_px[MAX_N];          // fp16: dinv[v]*x[v]  (200KB)
__device__ float   g_s[MAX_N];           // layer-1 aggregate accumulator
__device__ __half2 g_gd[MAX_N];          // fp16x2: dinv[v]*g[v,0:2] (400KB)
__device__ float2  g_acc[MAX_N];         // layer-2 aggregate accumulator (f32)

// no-return global reductions (REDG)
__device__ __forceinline__ void red_add_f32(float* addr, float v) {
    asm volatile("red.global.relaxed.gpu.add.f32 [%0], %1;"
                 :: "l"(addr), "f"(v) : "memory");
}
__device__ __forceinline__ void red_add_v2(float2* addr, float a, float b) {
    asm volatile("red.global.relaxed.gpu.add.v2.f32 [%0], {%1, %2};"
                 :: "l"(addr), "f"(a), "f"(b) : "memory");
}

__device__ __forceinline__ int4 ldcs_int4(const int* p) {
    return __ldcs(reinterpret_cast<const int4*>(p));
}

__device__ __forceinline__ void gdep_sync() {
#if __CUDA_ARCH__ >= 900
    cudaGridDependencySynchronize();
#endif
}

// degree histogram over dst, 4 edges/thread
// PDL prologue: dst loads (input array — independent of predecessor)
__global__ void k_deg(const int* __restrict__ dst, int E) {
    int i = blockIdx.x * blockDim.x + threadIdx.x;
    int base = i * 4;
    if (base + 3 < E) {
        int4 d = ldcs_int4(dst + base);
        gdep_sync();                       // wait for g_deg memset
        red_add_f32(&g_deg[d.x], 1.0f);
        red_add_f32(&g_deg[d.y], 1.0f);
        red_add_f32(&g_deg[d.z], 1.0f);
        red_add_f32(&g_deg[d.w], 1.0f);
    } else {
        gdep_sync();
        for (int j = base; j < E; ++j)
            red_add_f32(&g_deg[dst[j]], 1.0f);
    }
}

// PDL prologue: x load (input)
__global__ void k_dinv_px(const float* __restrict__ x, int n) {
    int i = blockIdx.x * blockDim.x + threadIdx.x;
    float xv = (i < n) ? x[i] : 0.0f;
    gdep_sync();                           // wait for k_deg
    if (i < n) {
        float dv = rsqrtf(g_deg[i] + 1.0f);   // +1 = self-loop
        g_dinv[i] = dv;
        g_px[i]   = __float2half_rn(dv * xv);
        g_s[i]    = 0.0f;                      // zero accumulator for scatter1
    }
}

// scatter 1: s[dst] += px[src], 4 edges/thread
// PDL prologue: src/dst loads (inputs)
__global__ void k_scatter1(const int* __restrict__ src,
                           const int* __restrict__ dst, int E) {
    int i = blockIdx.x * blockDim.x + threadIdx.x;
    int base = i * 4;
    if (base + 3 < E) {
        int4 s4 = ldcs_int4(src + base);
        int4 d4 = ldcs_int4(dst + base);
        gdep_sync();                       // wait for k_dinv_px (px, s=0)
        float p0 = __half2float(__ldg(&g_px[s4.x]));
        float p1 = __half2float(__ldg(&g_px[s4.y]));
        float p2 = __half2float(__ldg(&g_px[s4.z]));
        float p3 = __half2float(__ldg(&g_px[s4.w]));
        red_add_f32(&g_s[d4.x], p0);
        red_add_f32(&g_s[d4.y], p1);
        red_add_f32(&g_s[d4.z], p2);
        red_add_f32(&g_s[d4.w], p3);
    } else {
        gdep_sync();
        for (int j = base; j < E; ++j)
            red_add_f32(&g_s[dst[j]], __half2float(__ldg(&g_px[src[j]])));
    }
}

// per-node dense: finalize s, W1/b1 + relu, W2 -> g, pre-scale by dinv
// PDL prologue: weight loads (inputs)
__global__ void k_node(const float* __restrict__ W1, const float* __restrict__ b1,
                       const float* __restrict__ W2, int n) {
    int v = blockIdx.x * blockDim.x + threadIdx.x;
    float w1[HID], bb1[HID], w2a[HID], w2b[HID];
#pragma unroll
    for (int j = 0; j < HID; ++j) {
        w1[j]  = __ldg(&W1[j]);
        bb1[j] = __ldg(&b1[j]);
        w2a[j] = __ldg(&W2[2 * j + 0]);
        w2b[j] = __ldg(&W2[2 * j + 1]);
    }
    gdep_sync();                           // wait for k_scatter1
    if (v >= n) return;
    float dv = g_dinv[v];
    float sv = dv * (g_s[v] + __half2float(g_px[v]));  // + self-loop term
    float g0 = 0.0f, g1 = 0.0f;
#pragma unroll
    for (int j = 0; j < HID; ++j) {
        float h = fmaxf(fmaf(sv, w1[j], bb1[j]), 0.0f);
        g0 = fmaf(h, w2a[j], g0);
        g1 = fmaf(h, w2b[j], g1);
    }
    g_gd[v]  = __floats2half2_rn(dv * g0, dv * g1);
    g_acc[v] = make_float2(0.0f, 0.0f);                // zero for scatter2
}

// scatter 2: acc[dst] += gd[src] via ONE red.v2 per edge, 4 edges/thread
// PDL prologue: src/dst loads (inputs)
__global__ void k_scatter2(const int* __restrict__ src,
                           const int* __restrict__ dst, int E) {
    int i = blockIdx.x * blockDim.x + threadIdx.x;
    int base = i * 4;
    if (base + 3 < E) {
        int4 s4 = ldcs_int4(src + base);
        int4 d4 = ldcs_int4(dst + base);
        gdep_sync();                       // wait for k_node (gd, acc=0)
        float2 a0 = __half22float2(__ldg(&g_gd[s4.x]));
        float2 a1 = __half22float2(__ldg(&g_gd[s4.y]));
        float2 a2 = __half22float2(__ldg(&g_gd[s4.z]));
        float2 a3 = __half22float2(__ldg(&g_gd[s4.w]));
        red_add_v2(&g_acc[d4.x], a0.x, a0.y);
        red_add_v2(&g_acc[d4.y], a1.x, a1.y);
        red_add_v2(&g_acc[d4.z], a2.x, a2.y);
        red_add_v2(&g_acc[d4.w], a3.x, a3.y);
    } else {
        gdep_sync();
        for (int j = base; j < E; ++j) {
            float2 a = __half22float2(__ldg(&g_gd[src[j]]));
            red_add_v2(&g_acc[dst[j]], a.x, a.y);
        }
    }
}

// PDL prologue: bias loads (inputs)
__global__ void k_final(const float* __restrict__ b2, float* __restrict__ out, int n) {
    int v = blockIdx.x * blockDim.x + threadIdx.x;
    float c0 = __ldg(&b2[0]);
    float c1 = __ldg(&b2[1]);
    gdep_sync();                           // wait for k_scatter2
    if (v >= n) return;
    float dv = g_dinv[v];
    float2 acc = g_acc[v];
    float2 gd  = __half22float2(g_gd[v]);
    out[2 * v + 0] = dv * (acc.x + gd.x) + c0;
    out[2 * v + 1] = dv * (acc.y + gd.y) + c1;
}

// host-side helper: launch with PDL (programmatic stream serialization)
template <typename K, typename... Args>
static void launch_pdl(K kernel, dim3 grid, dim3 block, Args... args) {
    cudaLaunchConfig_t cfg = {};
    cfg.gridDim  = grid;
    cfg.blockDim = block;
    cfg.dynamicSmemBytes = 0;
    cfg.stream = 0;
    cudaLaunchAttribute attr[1];
    attr[0].id = cudaLaunchAttributeProgrammaticStreamSerialization;
    attr[0].val.programmaticStreamSerializationAllowed = 1;
    cfg.attrs = attr;
    cfg.numAttrs = 1;
    cudaLaunchKernelEx(&cfg, kernel, args...);
}

extern "C" void kernel_launch(void* const* d_in, const int* in_sizes, int n_in,
                              void* d_out, int out_size) {
    const float* x  = (const float*)d_in[0];
    const int*   ei = (const int*)d_in[1];       // [2, E]: row0=src, row1=dst
    const float* W1 = (const float*)d_in[2];
    const float* b1 = (const float*)d_in[3];
    const float* W2 = (const float*)d_in[4];
    const float* b2 = (const float*)d_in[5];
    float* out = (float*)d_out;

    int N = in_sizes[0];                 // C_IN = 1
    int E = in_sizes[1] / 2;
    const int* src = ei;
    const int* dst = ei + E;

    const int T = 256;
    int gridN  = (N + T - 1) / T;
    int E4     = (E + 3) / 4;
    int gridE4 = (E4 + T - 1) / T;

    // zero deg via DMA before the kernel chain
    void* degPtr = nullptr;
    cudaGetSymbolAddress(&degPtr, g_deg);
    cudaMemsetAsync(degPtr, 0, N * sizeof(float));

    launch_pdl(k_deg,      dim3(gridE4), dim3(T), dst, E);
    launch_pdl(k_dinv_px,  dim3(gridN),  dim3(T), x, N);
    launch_pdl(k_scatter1, dim3(gridE4), dim3(T), src, dst, E);
    launch_pdl(k_node,     dim3(gridN),  dim3(T), W1, b1, W2, N);
    launch_pdl(k_scatter2, dim3(gridE4), dim3(T), src, dst, E);
    launch_pdl(k_final,    dim3(gridN),  dim3(T), b2, out, N);
}